// round 4
// baseline (speedup 1.0000x reference)
#include <cuda_runtime.h>
#include <math.h>

#define BN_EPS 1e-5f

// ---------------------------------------------------------------------------
// Static device scratch (allocation-free rule: __device__ globals)
// ---------------------------------------------------------------------------
__device__ float g_bufA[131072 * 128];
__device__ float g_bufB[131072 * 128];
__device__ float g_f1[8 * 512 * 128];
__device__ float g_f2[8 * 128 * 256];
__device__ float g_sa3in[1024 * 259];
__device__ float g_gfeat[8 * 128];
__device__ float g_objfeat[8 * 1024];
__device__ float g_comb[8 * 1152];
__device__ float g_h0[8 * 512];
__device__ float g_h1[8 * 256];
__device__ float g_xyz1[8 * 512 * 3];
__device__ float g_xyz2[8 * 128 * 3];
__device__ int   g_fps1[8 * 512];
__device__ int   g_fps2[8 * 128];
__device__ int   g_bq1[8 * 512 * 32];
__device__ int   g_bq2[8 * 128 * 64];
__device__ float g_bnsum[1024];
__device__ float g_bnsq[1024];

// ---------------------------------------------------------------------------
// GEMM:  Y[M,N] = X[M,K] * W[N,K]^T  (+bias, +relu optional)
// 64x64 tile, TK=16, 256 threads, 4x4 microtile.
// ---------------------------------------------------------------------------
__global__ __launch_bounds__(256) void gemm_kernel(
    const float* __restrict__ X, const float* __restrict__ W,
    const float* __restrict__ bias, float* __restrict__ Y,
    int M, int N, int K, int relu)
{
    __shared__ __align__(16) float As[16][68];
    __shared__ __align__(16) float Bs[16][68];
    const int bm = blockIdx.y * 64;
    const int bn = blockIdx.x * 64;
    const int t  = threadIdx.x;
    const int ty = t >> 4;   // 0..15
    const int tx = t & 15;   // 0..15
    float acc[4][4];
#pragma unroll
    for (int i = 0; i < 4; i++)
#pragma unroll
        for (int j = 0; j < 4; j++) acc[i][j] = 0.f;

    for (int k0 = 0; k0 < K; k0 += 16) {
#pragma unroll
        for (int i = 0; i < 4; i++) {
            int lin = i * 256 + t;       // 0..1023
            int r = lin >> 4;            // 0..63
            int c = lin & 15;            // 0..15
            int gk = k0 + c;
            float v = 0.f, w = 0.f;
            if (gk < K) {
                int gm = bm + r;
                int gn = bn + r;
                if (gm < M) v = X[(size_t)gm * K + gk];
                if (gn < N) w = W[(size_t)gn * K + gk];
            }
            As[c][r] = v;
            Bs[c][r] = w;
        }
        __syncthreads();
#pragma unroll
        for (int kk = 0; kk < 16; kk++) {
            float4 av = *reinterpret_cast<const float4*>(&As[kk][ty * 4]);
            float4 bv = *reinterpret_cast<const float4*>(&Bs[kk][tx * 4]);
            float a[4] = {av.x, av.y, av.z, av.w};
            float b[4] = {bv.x, bv.y, bv.z, bv.w};
#pragma unroll
            for (int i = 0; i < 4; i++)
#pragma unroll
                for (int j = 0; j < 4; j++)
                    acc[i][j] = fmaf(a[i], b[j], acc[i][j]);
        }
        __syncthreads();
    }
#pragma unroll
    for (int i = 0; i < 4; i++) {
        int gm = bm + ty * 4 + i;
        if (gm >= M) continue;
#pragma unroll
        for (int j = 0; j < 4; j++) {
            int gn = bn + tx * 4 + j;
            if (gn >= N) continue;
            float v = acc[i][j];
            if (bias) v += bias[gn];
            if (relu) v = fmaxf(v, 0.f);
            Y[(size_t)gm * N + gn] = v;
        }
    }
}

// ---------------------------------------------------------------------------
// BatchNorm (training-mode, gamma=1 beta=0) — big-M path via atomics
// ---------------------------------------------------------------------------
__global__ void bn_zero_kernel(float* s, float* q, int C)
{
    for (int i = threadIdx.x; i < C; i += blockDim.x) { s[i] = 0.f; q[i] = 0.f; }
}

__global__ void bn_stats_kernel(const float* __restrict__ X,
                                float* __restrict__ gsum, float* __restrict__ gsq,
                                unsigned M, int C)
{
    extern __shared__ float sh[];
    float* ss = sh;
    float* sq = sh + C;
    for (int i = threadIdx.x; i < 2 * C; i += blockDim.x) sh[i] = 0.f;
    __syncthreads();
    unsigned total = M * (unsigned)C;
    unsigned stride = gridDim.x * blockDim.x;
    for (unsigned i = blockIdx.x * blockDim.x + threadIdx.x; i < total; i += stride) {
        float v = X[i];
        int c = (int)(i % (unsigned)C);
        atomicAdd(&ss[c], v);
        atomicAdd(&sq[c], v * v);
    }
    __syncthreads();
    for (int i = threadIdx.x; i < C; i += blockDim.x) {
        atomicAdd(&gsum[i], ss[i]);
        atomicAdd(&gsq[i], sq[i]);
    }
}

__global__ void bn_norm_kernel(float* __restrict__ X,
                               const float* __restrict__ gsum, const float* __restrict__ gsq,
                               unsigned M, int C, int relu)
{
    unsigned total = M * (unsigned)C;
    unsigned stride = gridDim.x * blockDim.x;
    float invM = 1.f / (float)M;   // M is a power of two here -> exact
    for (unsigned i = blockIdx.x * blockDim.x + threadIdx.x; i < total; i += stride) {
        int c = (int)(i % (unsigned)C);
        float mean = gsum[c] * invM;
        float var = fmaxf(gsq[c] * invM - mean * mean, 0.f);
        float v = (X[i] - mean) * (1.f / sqrtf(var + BN_EPS));
        if (relu) v = fmaxf(v, 0.f);
        X[i] = v;
    }
}

// exact per-column BN for small M (<= 1024)
__global__ void bn_col_kernel(float* __restrict__ X, int M, int C, int relu)
{
    int c = blockIdx.x * blockDim.x + threadIdx.x;
    if (c >= C) return;
    float s = 0.f, q = 0.f;
    for (int m = 0; m < M; m++) {
        float v = X[(size_t)m * C + c];
        s += v;
        q = fmaf(v, v, q);
    }
    float mean = s / (float)M;
    float var = fmaxf(q / (float)M - mean * mean, 0.f);
    float inv = 1.f / sqrtf(var + BN_EPS);
    for (int m = 0; m < M; m++) {
        float v = (X[(size_t)m * C + c] - mean) * inv;
        if (relu) v = fmaxf(v, 0.f);
        X[(size_t)m * C + c] = v;
    }
}

// ---------------------------------------------------------------------------
// Max pool over the group axis: X[R, ns, C] -> Y[R, C]
// ---------------------------------------------------------------------------
__global__ void maxpool_kernel(const float* __restrict__ X, float* __restrict__ Y,
                               int R, int ns, int C)
{
    unsigned total = (unsigned)R * C;
    unsigned stride = gridDim.x * blockDim.x;
    for (unsigned e = blockIdx.x * blockDim.x + threadIdx.x; e < total; e += stride) {
        int r = e / C;
        int c = e % C;
        const float* p = X + ((size_t)r * ns) * C + c;
        float m = -3.402823466e38f;
        for (int j = 0; j < ns; j++) m = fmaxf(m, p[(size_t)j * C]);
        Y[e] = m;
    }
}

// ---------------------------------------------------------------------------
// Farthest point sampling — one block per batch, serial over npoint steps.
// Exactly matches jnp semantics: d = (dx*dx + dy*dy) + dz*dz (no FMA),
// dists = min(dists, d), argmax = first occurrence of max.
// ---------------------------------------------------------------------------
template <int PPT>
__global__ void __launch_bounds__(1024) fps_kernel(
    const float* __restrict__ xyz, int N, int npoint,
    int* __restrict__ idx_out, float* __restrict__ newxyz)
{
    const int b = blockIdx.x;
    const int T = blockDim.x;
    const int t = threadIdx.x;
    const float* P = xyz + (size_t)b * N * 3;

    float dist[PPT];
#pragma unroll
    for (int k = 0; k < PPT; k++) dist[k] = 1e10f;

    __shared__ float s_v[32];
    __shared__ int   s_i[32];
    __shared__ float s_far[3];
    __shared__ int   s_faridx;
    if (t == 0) s_faridx = 0;
    __syncthreads();

    for (int it = 0; it < npoint; it++) {
        if (t == 0) {
            int far = s_faridx;
            float fx = P[far * 3 + 0];
            float fy = P[far * 3 + 1];
            float fz = P[far * 3 + 2];
            idx_out[b * npoint + it] = far;
            newxyz[((size_t)b * npoint + it) * 3 + 0] = fx;
            newxyz[((size_t)b * npoint + it) * 3 + 1] = fy;
            newxyz[((size_t)b * npoint + it) * 3 + 2] = fz;
            s_far[0] = fx; s_far[1] = fy; s_far[2] = fz;
        }
        __syncthreads();
        float fx = s_far[0], fy = s_far[1], fz = s_far[2];
        float best = -1.f;
        int bi = 0x7fffffff;
#pragma unroll
        for (int k = 0; k < PPT; k++) {
            int p = t + k * T;
            if (p < N) {
                float dx = __fsub_rn(P[p * 3 + 0], fx);
                float dy = __fsub_rn(P[p * 3 + 1], fy);
                float dz = __fsub_rn(P[p * 3 + 2], fz);
                float d = __fadd_rn(__fadd_rn(__fmul_rn(dx, dx), __fmul_rn(dy, dy)),
                                    __fmul_rn(dz, dz));
                float nd = fminf(dist[k], d);
                dist[k] = nd;
                if (nd > best) { best = nd; bi = p; }   // strict > keeps smallest p
            }
        }
        // warp argmax (ties -> smaller index)
#pragma unroll
        for (int o = 16; o > 0; o >>= 1) {
            float ov = __shfl_down_sync(0xffffffffu, best, o);
            int   oi = __shfl_down_sync(0xffffffffu, bi, o);
            if (ov > best || (ov == best && oi < bi)) { best = ov; bi = oi; }
        }
        if ((t & 31) == 0) { s_v[t >> 5] = best; s_i[t >> 5] = bi; }
        __syncthreads();
        if (t < 32) {
            int nw = T >> 5;
            best = (t < nw) ? s_v[t] : -1.f;
            bi   = (t < nw) ? s_i[t] : 0x7fffffff;
#pragma unroll
            for (int o = 16; o > 0; o >>= 1) {
                float ov = __shfl_down_sync(0xffffffffu, best, o);
                int   oi = __shfl_down_sync(0xffffffffu, bi, o);
                if (ov > best || (ov == best && oi < bi)) { best = ov; bi = oi; }
            }
            if (t == 0) s_faridx = bi;
        }
        __syncthreads();
    }
}

// ---------------------------------------------------------------------------
// Ball query — one warp per center; first nsample indices (ascending order)
// with d2 < r2; pad with first valid index.
// ---------------------------------------------------------------------------
__global__ void ballquery_kernel(const float* __restrict__ centers,
                                 const float* __restrict__ pts,
                                 int B, int S, int N, float r2, int nsample,
                                 int* __restrict__ out)
{
    int wg = (blockIdx.x * blockDim.x + threadIdx.x) >> 5;
    int lane = threadIdx.x & 31;
    if (wg >= B * S) return;
    int b = wg / S;
    const float* P = pts + (size_t)b * N * 3;
    float cx = centers[(size_t)wg * 3 + 0];
    float cy = centers[(size_t)wg * 3 + 1];
    float cz = centers[(size_t)wg * 3 + 2];
    int* o = out + (size_t)wg * nsample;

    int count = 0;
    int first = -1;
    for (int base = 0; base < N && count < nsample; base += 32) {
        int p = base + lane;
        bool inside = false;
        if (p < N) {
            float dx = __fsub_rn(cx, P[p * 3 + 0]);
            float dy = __fsub_rn(cy, P[p * 3 + 1]);
            float dz = __fsub_rn(cz, P[p * 3 + 2]);
            float d2 = __fadd_rn(__fadd_rn(__fmul_rn(dx, dx), __fmul_rn(dy, dy)),
                                 __fmul_rn(dz, dz));
            inside = d2 < r2;
        }
        unsigned m = __ballot_sync(0xffffffffu, inside);
        if (first < 0 && m) first = base + __ffs(m) - 1;
        if (inside) {
            int pos = count + __popc(m & ((1u << lane) - 1u));
            if (pos < nsample) o[pos] = p;
        }
        count += __popc(m);
    }
    int start = count < nsample ? count : nsample;
    for (int k = start + lane; k < nsample; k += 32) o[k] = first;
}

// ---------------------------------------------------------------------------
// Grouping / concat kernels
// ---------------------------------------------------------------------------
__global__ void group_xyz_kernel(const float* __restrict__ pts,
                                 const float* __restrict__ centers,
                                 const int* __restrict__ idx,
                                 float* __restrict__ out,
                                 int B, int S, int N, int ns, float radius)
{
    unsigned total = (unsigned)B * S * ns * 3;
    unsigned stride = gridDim.x * blockDim.x;
    for (unsigned e = blockIdx.x * blockDim.x + threadIdx.x; e < total; e += stride) {
        int d = e % 3;
        unsigned g = e / 3;           // center-group element index (B*S*ns)
        int pid = idx[g];
        unsigned cidx = g / ns;       // B*S
        int b = cidx / S;
        float v = __fsub_rn(pts[((size_t)b * N + pid) * 3 + d], centers[(size_t)cidx * 3 + d]);
        out[e] = __fdiv_rn(v, radius);
    }
}

__global__ void group_feat_kernel(const float* __restrict__ pts,
                                  const float* __restrict__ centers,
                                  const int* __restrict__ idx,
                                  const float* __restrict__ feats,
                                  float* __restrict__ out,
                                  int B, int S, int N, int ns, int CF, float radius)
{
    int C = 3 + CF;
    unsigned total = (unsigned)B * S * ns * C;
    unsigned stride = gridDim.x * blockDim.x;
    for (unsigned e = blockIdx.x * blockDim.x + threadIdx.x; e < total; e += stride) {
        int c = e % C;
        unsigned g = e / C;
        int pid = idx[g];
        unsigned cidx = g / ns;
        int b = cidx / S;
        float v;
        if (c < 3) {
            v = __fdiv_rn(__fsub_rn(pts[((size_t)b * N + pid) * 3 + c],
                                    centers[(size_t)cidx * 3 + c]), radius);
        } else {
            v = feats[((size_t)b * N + pid) * CF + (c - 3)];
        }
        out[e] = v;
    }
}

__global__ void concat_sa3_kernel(const float* __restrict__ xyz2,
                                  const float* __restrict__ f2,
                                  float* __restrict__ out, int R, int CF)
{
    int C = 3 + CF;
    unsigned total = (unsigned)R * C;
    unsigned stride = gridDim.x * blockDim.x;
    for (unsigned e = blockIdx.x * blockDim.x + threadIdx.x; e < total; e += stride) {
        int r = e / C;
        int c = e % C;
        out[e] = (c < 3) ? xyz2[(size_t)r * 3 + c] : f2[(size_t)r * CF + (c - 3)];
    }
}

__global__ void concat_comb_kernel(const float* __restrict__ gf,
                                   const float* __restrict__ of,
                                   float* __restrict__ out, int B, int C1, int C2)
{
    int C = C1 + C2;
    unsigned total = (unsigned)B * C;
    unsigned stride = gridDim.x * blockDim.x;
    for (unsigned e = blockIdx.x * blockDim.x + threadIdx.x; e < total; e += stride) {
        int b = e / C;
        int c = e % C;
        out[e] = (c < C1) ? gf[(size_t)b * C1 + c] : of[(size_t)b * C2 + (c - C1)];
    }
}

// ---------------------------------------------------------------------------
// Host-side launch orchestration
// ---------------------------------------------------------------------------
static inline int cdiv(long a, long b) { return (int)((a + b - 1) / b); }

static void launch_gemm(const float* X, const float* W, const float* bias, float* Y,
                        int M, int N, int K, int relu)
{
    dim3 grid(cdiv(N, 64), cdiv(M, 64));
    gemm_kernel<<<grid, 256>>>(X, W, bias, Y, M, N, K, relu);
}

static void launch_bn_big(float* X, unsigned M, int C, int relu, float* bsum, float* bsq)
{
    bn_zero_kernel<<<1, 256>>>(bsum, bsq, C);
    bn_stats_kernel<<<256, 256, 2 * C * sizeof(float)>>>(X, bsum, bsq, M, C);
    long total = (long)M * C;
    int blocks = cdiv(total, 256);
    if (blocks > 4096) blocks = 4096;
    bn_norm_kernel<<<blocks, 256>>>(X, bsum, bsq, M, C, relu);
}

static int ew_blocks(long total)
{
    int b = cdiv(total, 256);
    return b > 4096 ? 4096 : b;
}

extern "C" void kernel_launch(void* const* d_in, const int* in_sizes, int n_in,
                              void* d_out, int out_size)
{
    (void)in_sizes; (void)n_in; (void)out_size;
    const float* obj   = (const float*)d_in[0];   // [8,20000,3]
    const float* grip  = (const float*)d_in[1];   // [8,512,3]
    const float* sa1w0 = (const float*)d_in[2];
    const float* sa1w1 = (const float*)d_in[3];
    const float* sa1w2 = (const float*)d_in[4];
    const float* sa2w0 = (const float*)d_in[5];
    const float* sa2w1 = (const float*)d_in[6];
    const float* sa2w2 = (const float*)d_in[7];
    const float* sa3w0 = (const float*)d_in[8];
    const float* sa3w1 = (const float*)d_in[9];
    const float* sa3w2 = (const float*)d_in[10];
    const float* gew0  = (const float*)d_in[11];
    const float* gew1  = (const float*)d_in[12];
    const float* gew2  = (const float*)d_in[13];
    const float* hw0   = (const float*)d_in[14];
    const float* hb0   = (const float*)d_in[15];
    const float* hw1   = (const float*)d_in[16];
    const float* hb1   = (const float*)d_in[17];
    const float* hw2   = (const float*)d_in[18];
    const float* hb2   = (const float*)d_in[19];

    float *bufA, *bufB, *f1, *f2, *sa3in, *gfeat, *objf, *comb, *h0, *h1;
    float *xyz1, *xyz2, *bsum, *bsq;
    int *fps1, *fps2, *bq1, *bq2;
    cudaGetSymbolAddress((void**)&bufA,  g_bufA);
    cudaGetSymbolAddress((void**)&bufB,  g_bufB);
    cudaGetSymbolAddress((void**)&f1,    g_f1);
    cudaGetSymbolAddress((void**)&f2,    g_f2);
    cudaGetSymbolAddress((void**)&sa3in, g_sa3in);
    cudaGetSymbolAddress((void**)&gfeat, g_gfeat);
    cudaGetSymbolAddress((void**)&objf,  g_objfeat);
    cudaGetSymbolAddress((void**)&comb,  g_comb);
    cudaGetSymbolAddress((void**)&h0,    g_h0);
    cudaGetSymbolAddress((void**)&h1,    g_h1);
    cudaGetSymbolAddress((void**)&xyz1,  g_xyz1);
    cudaGetSymbolAddress((void**)&xyz2,  g_xyz2);
    cudaGetSymbolAddress((void**)&fps1,  g_fps1);
    cudaGetSymbolAddress((void**)&fps2,  g_fps2);
    cudaGetSymbolAddress((void**)&bq1,   g_bq1);
    cudaGetSymbolAddress((void**)&bq2,   g_bq2);
    cudaGetSymbolAddress((void**)&bsum,  g_bnsum);
    cudaGetSymbolAddress((void**)&bsq,   g_bnsq);

    const int B = 8, N0 = 20000, G = 512;
    const int S1 = 512, NS1 = 32, S2 = 128, NS2 = 64;
    const float r2_1 = (float)(0.2 * 0.2);
    const float r2_2 = (float)(0.4 * 0.4);

    // ---------------- gripper encoder: [8,512,3] -> [8,128] ----------------
    {
        int M = B * G;  // 4096
        launch_gemm(grip, gew0, nullptr, bufB, M, 64, 3, 0);
        launch_bn_big(bufB, M, 64, 1, bsum, bsq);
        launch_gemm(bufB, gew1, nullptr, bufA, M, 128, 64, 0);
        launch_bn_big(bufA, M, 128, 1, bsum, bsq);
        launch_gemm(bufA, gew2, nullptr, bufB, M, 128, 128, 0);
        launch_bn_big(bufB, M, 128, 1, bsum, bsq);
        maxpool_kernel<<<ew_blocks((long)B * 128), 256>>>(bufB, gfeat, B, G, 128);
    }

    // ---------------- SA1: 20000 -> 512 centers, ns=32, r=0.2 ----------------
    fps_kernel<20><<<B, 1024>>>(obj, N0, S1, fps1, xyz1);
    {
        int warps = B * S1;
        ballquery_kernel<<<cdiv((long)warps * 32, 128), 128>>>(xyz1, obj, B, S1, N0, r2_1, NS1, bq1);
        long gtot = (long)B * S1 * NS1 * 3;
        group_xyz_kernel<<<ew_blocks(gtot), 256>>>(obj, xyz1, bq1, bufA, B, S1, N0, NS1, 0.2f);

        unsigned M = (unsigned)B * S1 * NS1;  // 131072
        launch_gemm(bufA, sa1w0, nullptr, bufB, M, 64, 3, 0);
        launch_bn_big(bufB, M, 64, 1, bsum, bsq);
        launch_gemm(bufB, sa1w1, nullptr, bufA, M, 64, 64, 0);
        launch_bn_big(bufA, M, 64, 1, bsum, bsq);
        launch_gemm(bufA, sa1w2, nullptr, bufB, M, 128, 64, 0);
        launch_bn_big(bufB, M, 128, 1, bsum, bsq);
        maxpool_kernel<<<ew_blocks((long)B * S1 * 128), 256>>>(bufB, f1, B * S1, NS1, 128);
    }

    // ---------------- SA2: 512 -> 128 centers, ns=64, r=0.4 ----------------
    fps_kernel<1><<<B, 512>>>(xyz1, S1, S2, fps2, xyz2);
    {
        int warps = B * S2;
        ballquery_kernel<<<cdiv((long)warps * 32, 128), 128>>>(xyz2, xyz1, B, S2, S1, r2_2, NS2, bq2);
        long gtot = (long)B * S2 * NS2 * 131;
        group_feat_kernel<<<ew_blocks(gtot), 256>>>(xyz1, xyz2, bq2, f1, bufA,
                                                    B, S2, S1, NS2, 128, 0.4f);

        unsigned M = (unsigned)B * S2 * NS2;  // 65536
        launch_gemm(bufA, sa2w0, nullptr, bufB, M, 128, 131, 0);
        launch_bn_big(bufB, M, 128, 1, bsum, bsq);
        launch_gemm(bufB, sa2w1, nullptr, bufA, M, 128, 128, 0);
        launch_bn_big(bufA, M, 128, 1, bsum, bsq);
        launch_gemm(bufA, sa2w2, nullptr, bufB, M, 256, 128, 0);
        launch_bn_big(bufB, M, 256, 1, bsum, bsq);
        maxpool_kernel<<<ew_blocks((long)B * S2 * 256), 256>>>(bufB, f2, B * S2, NS2, 256);
    }

    // ---------------- SA3: group_all on [8,128,259] ----------------
    {
        int M = B * S2;  // 1024
        concat_sa3_kernel<<<ew_blocks((long)M * 259), 256>>>(xyz2, f2, sa3in, M, 256);
        launch_gemm(sa3in, sa3w0, nullptr, bufA, M, 256, 259, 0);
        bn_col_kernel<<<cdiv(256, 256), 256>>>(bufA, M, 256, 1);
        launch_gemm(bufA, sa3w1, nullptr, bufB, M, 512, 256, 0);
        bn_col_kernel<<<cdiv(512, 256), 256>>>(bufB, M, 512, 1);
        launch_gemm(bufB, sa3w2, nullptr, bufA, M, 1024, 512, 0);
        bn_col_kernel<<<cdiv(1024, 256), 256>>>(bufA, M, 1024, 1);
        maxpool_kernel<<<ew_blocks((long)B * 1024), 256>>>(bufA, objf, B, S2, 1024);
    }

    // ---------------- head ----------------
    {
        concat_comb_kernel<<<ew_blocks((long)B * 1152), 256>>>(gfeat, objf, comb, B, 128, 1024);
        bn_col_kernel<<<cdiv(1152, 256), 256>>>(comb, B, 1152, 0);            // bn, no relu
        launch_gemm(comb, hw0, hb0, h0, B, 512, 1152, 0);
        bn_col_kernel<<<cdiv(512, 256), 256>>>(h0, B, 512, 1);                // bn + relu
        launch_gemm(h0, hw1, hb1, h1, B, 256, 512, 0);
        bn_col_kernel<<<cdiv(256, 256), 256>>>(h1, B, 256, 1);                // bn + relu
        launch_gemm(h1, hw2, hb2, (float*)d_out, B, 1, 256, 1);               // + relu
    }
}

// round 5
// speedup vs baseline: 1.5380x; 1.5380x over previous
#include <cuda_runtime.h>
#include <math.h>

#define BN_EPS 1e-5f

// ---------------------------------------------------------------------------
// Static device scratch
// ---------------------------------------------------------------------------
__device__ float g_bufA[131072 * 128];
__device__ float g_bufB[131072 * 128];
__device__ float g_f1[8 * 512 * 128];
__device__ float g_f2[8 * 128 * 256];
__device__ float g_sa3in[1024 * 259];
__device__ float g_gfeat[8 * 128];
__device__ float g_objfeat[8 * 1024];
__device__ float g_comb[8 * 1152];
__device__ float g_h0[8 * 512];
__device__ float g_h1[8 * 256];
__device__ float g_xyz1[8 * 512 * 3];
__device__ float g_xyz2[8 * 128 * 3];
__device__ int   g_fps1[8 * 512];
__device__ int   g_fps2[8 * 128];
__device__ int   g_bq1[8 * 512 * 32];
__device__ int   g_bq2[8 * 128 * 64];
__device__ float g_bnsum[1024];
__device__ float g_bnsq[1024];
__device__ float g_bnmean[1024];
__device__ float g_bninv[1024];

// ---------------------------------------------------------------------------
// Fused GEMM:  Y[M,N] = f(X)[M,K] * W[N,K]^T
//   input transform (optional):  x -> relu((x - inMean[k]) * inInv[k])
//   epilogue (optional): bias add, relu, per-column sum/sumsq accumulation
// BM=128, BN=64, BK=16, TM=8, TN=4, 256 threads.
// ---------------------------------------------------------------------------
__global__ __launch_bounds__(256) void gemm_fused_kernel(
    const float* __restrict__ X, const float* __restrict__ W,
    const float* __restrict__ bias, float* __restrict__ Y,
    int M, int N, int K,
    const float* __restrict__ inMean, const float* __restrict__ inInv,
    float* __restrict__ gsum, float* __restrict__ gsq,
    int relu_out)
{
    __shared__ __align__(16) float As[16][132];
    __shared__ __align__(16) float Bs[16][68];
    __shared__ float sSum[64];
    __shared__ float sSq[64];

    const int bm = blockIdx.y * 128;
    const int bn = blockIdx.x * 64;
    const int t  = threadIdx.x;
    const int ty = t >> 4;   // 0..15 -> m microrow * 8
    const int tx = t & 15;   // 0..15 -> n microcol * 4

    float acc[8][4];
#pragma unroll
    for (int i = 0; i < 8; i++)
#pragma unroll
        for (int j = 0; j < 4; j++) acc[i][j] = 0.f;

    for (int k0 = 0; k0 < K; k0 += 16) {
        // load X tile (128 x 16) with optional BN-relu transform
#pragma unroll
        for (int i = 0; i < 8; i++) {
            int lin = i * 256 + t;
            int r = lin >> 4;
            int c = lin & 15;
            int gm = bm + r, gk = k0 + c;
            float v = 0.f;
            if (gk < K && gm < M) {
                v = X[(size_t)gm * K + gk];
                if (inMean) v = fmaxf(0.f, (v - inMean[gk]) * inInv[gk]);
            }
            As[c][r] = v;
        }
        // load W tile (64 x 16)
#pragma unroll
        for (int i = 0; i < 4; i++) {
            int lin = i * 256 + t;
            int r = lin >> 4;
            int c = lin & 15;
            int gn = bn + r, gk = k0 + c;
            float w = 0.f;
            if (gk < K && gn < N) w = W[(size_t)gn * K + gk];
            Bs[c][r] = w;
        }
        __syncthreads();
#pragma unroll
        for (int kk = 0; kk < 16; kk++) {
            float4 a0 = *reinterpret_cast<const float4*>(&As[kk][ty * 8]);
            float4 a1 = *reinterpret_cast<const float4*>(&As[kk][ty * 8 + 4]);
            float4 bv = *reinterpret_cast<const float4*>(&Bs[kk][tx * 4]);
            float a[8] = {a0.x, a0.y, a0.z, a0.w, a1.x, a1.y, a1.z, a1.w};
            float b[4] = {bv.x, bv.y, bv.z, bv.w};
#pragma unroll
            for (int i = 0; i < 8; i++)
#pragma unroll
                for (int j = 0; j < 4; j++)
                    acc[i][j] = fmaf(a[i], b[j], acc[i][j]);
        }
        __syncthreads();
    }

    // epilogue: store + per-column stats
    float colS[4] = {0.f, 0.f, 0.f, 0.f};
    float colQ[4] = {0.f, 0.f, 0.f, 0.f};
#pragma unroll
    for (int i = 0; i < 8; i++) {
        int gm = bm + ty * 8 + i;
        if (gm >= M) continue;
#pragma unroll
        for (int j = 0; j < 4; j++) {
            int gn = bn + tx * 4 + j;
            if (gn >= N) continue;
            float v = acc[i][j];
            if (bias) v += bias[gn];
            if (relu_out) v = fmaxf(v, 0.f);
            Y[(size_t)gm * N + gn] = v;
            colS[j] += v;
            colQ[j] = fmaf(v, v, colQ[j]);
        }
    }

    if (gsum) {
        // reduce over the two ty rows sharing a warp
#pragma unroll
        for (int j = 0; j < 4; j++) {
            colS[j] += __shfl_down_sync(0xffffffffu, colS[j], 16);
            colQ[j] += __shfl_down_sync(0xffffffffu, colQ[j], 16);
        }
        if (t < 64) { sSum[t] = 0.f; sSq[t] = 0.f; }
        __syncthreads();
        if ((t & 31) < 16) {
#pragma unroll
            for (int j = 0; j < 4; j++) {
                atomicAdd(&sSum[tx * 4 + j], colS[j]);
                atomicAdd(&sSq[tx * 4 + j], colQ[j]);
            }
        }
        __syncthreads();
        if (t < 64) {
            int gn = bn + t;
            if (gn < N) {
                atomicAdd(&gsum[gn], sSum[t]);
                atomicAdd(&gsq[gn], sSq[t]);
            }
        }
    }
}

// ---------------------------------------------------------------------------
// BN helpers
// ---------------------------------------------------------------------------
__global__ void bn_zero_kernel(float* s, float* q, int C)
{
    for (int i = threadIdx.x; i < C; i += blockDim.x) { s[i] = 0.f; q[i] = 0.f; }
}

__global__ void bn_finalize_kernel(float* __restrict__ gsum, float* __restrict__ gsq,
                                   float* __restrict__ mean, float* __restrict__ inv,
                                   int C, float invM)
{
    int c = blockIdx.x * blockDim.x + threadIdx.x;
    if (c >= C) return;
    float m = gsum[c] * invM;
    float var = fmaxf(gsq[c] * invM - m * m, 0.f);
    mean[c] = m;
    inv[c] = 1.f / sqrtf(var + BN_EPS);
    gsum[c] = 0.f;   // ready for the next layer
    gsq[c] = 0.f;
}

// exact per-column BN for small M (head path)
__global__ void bn_col_kernel(float* __restrict__ X, int M, int C, int relu)
{
    int c = blockIdx.x * blockDim.x + threadIdx.x;
    if (c >= C) return;
    float s = 0.f, q = 0.f;
    for (int m = 0; m < M; m++) {
        float v = X[(size_t)m * C + c];
        s += v;
        q = fmaf(v, v, q);
    }
    float mean = s / (float)M;
    float var = fmaxf(q / (float)M - mean * mean, 0.f);
    float inv = 1.f / sqrtf(var + BN_EPS);
    for (int m = 0; m < M; m++) {
        float v = (X[(size_t)m * C + c] - mean) * inv;
        if (relu) v = fmaxf(v, 0.f);
        X[(size_t)m * C + c] = v;
    }
}

// ---------------------------------------------------------------------------
// Max pool over the group axis with fused BN+ReLU (monotone, so pool first)
// X[R, ns, C] (pre-norm) -> Y[R, C] = relu((max_j X - mean[c]) * inv[c])
// ---------------------------------------------------------------------------
__global__ void maxpool_bn_kernel(const float* __restrict__ X, float* __restrict__ Y,
                                  int R, int ns, int C,
                                  const float* __restrict__ mean,
                                  const float* __restrict__ inv)
{
    unsigned total = (unsigned)R * C;
    unsigned stride = gridDim.x * blockDim.x;
    for (unsigned e = blockIdx.x * blockDim.x + threadIdx.x; e < total; e += stride) {
        int r = e / C;
        int c = e % C;
        const float* p = X + ((size_t)r * ns) * C + c;
        float m = -3.402823466e38f;
        for (int j = 0; j < ns; j++) m = fmaxf(m, p[(size_t)j * C]);
        Y[e] = fmaxf(0.f, (m - mean[c]) * inv[c]);
    }
}

// ---------------------------------------------------------------------------
// FPS1: one block per batch, 512 threads, 40 pts/thread.
// xy resident in dynamic smem (160KB), z + running min-dist in registers.
// Exact non-FMA distance math; argmax ties -> smallest index.
// ---------------------------------------------------------------------------
__global__ void __launch_bounds__(512) fps1_kernel(
    const float* __restrict__ xyz, int N, int npoint,
    int* __restrict__ idx_out, float* __restrict__ newxyz)
{
    extern __shared__ float2 sxy[];
    const int b = blockIdx.x;
    const int T = 512;
    const int t = threadIdx.x;
    const float* P = xyz + (size_t)b * N * 3;

    __shared__ float s_v[16];
    __shared__ int   s_i[16];
    __shared__ float s_far[3];
    __shared__ int   s_faridx;

    // load xy into smem
    for (int p = t; p < N; p += T)
        sxy[p] = make_float2(P[p * 3 + 0], P[p * 3 + 1]);

    float zreg[40];
    float dist[40];
#pragma unroll
    for (int k = 0; k < 40; k++) {
        int p = t + k * T;
        zreg[k] = (p < N) ? P[p * 3 + 2] : 0.f;
        dist[k] = 1e10f;
    }
    if (t == 0) s_faridx = 0;
    __syncthreads();

    for (int it = 0; it < npoint; it++) {
        if (t == 0) {
            int far = s_faridx;
            float2 fxy = sxy[far];
            float fz = P[far * 3 + 2];
            idx_out[b * npoint + it] = far;
            newxyz[((size_t)b * npoint + it) * 3 + 0] = fxy.x;
            newxyz[((size_t)b * npoint + it) * 3 + 1] = fxy.y;
            newxyz[((size_t)b * npoint + it) * 3 + 2] = fz;
            s_far[0] = fxy.x; s_far[1] = fxy.y; s_far[2] = fz;
        }
        __syncthreads();
        float fx = s_far[0], fy = s_far[1], fz = s_far[2];
        float best = -1.f;
        int bi = 0x7fffffff;
#pragma unroll
        for (int k = 0; k < 40; k++) {
            int p = t + k * T;
            if (p < N) {
                float2 xy = sxy[p];
                float dx = __fsub_rn(xy.x, fx);
                float dy = __fsub_rn(xy.y, fy);
                float dz = __fsub_rn(zreg[k], fz);
                float d = __fadd_rn(__fadd_rn(__fmul_rn(dx, dx), __fmul_rn(dy, dy)),
                                    __fmul_rn(dz, dz));
                float nd = fminf(dist[k], d);
                dist[k] = nd;
                if (nd > best) { best = nd; bi = p; }  // strict > keeps smallest p
            }
        }
#pragma unroll
        for (int o = 16; o > 0; o >>= 1) {
            float ov = __shfl_down_sync(0xffffffffu, best, o);
            int   oi = __shfl_down_sync(0xffffffffu, bi, o);
            if (ov > best || (ov == best && oi < bi)) { best = ov; bi = oi; }
        }
        if ((t & 31) == 0) { s_v[t >> 5] = best; s_i[t >> 5] = bi; }
        __syncthreads();
        if (t < 32) {
            best = (t < 16) ? s_v[t] : -1.f;
            bi   = (t < 16) ? s_i[t] : 0x7fffffff;
#pragma unroll
            for (int o = 8; o > 0; o >>= 1) {
                float ov = __shfl_down_sync(0xffffffffu, best, o);
                int   oi = __shfl_down_sync(0xffffffffu, bi, o);
                if (ov > best || (ov == best && oi < bi)) { best = ov; bi = oi; }
            }
            if (t == 0) s_faridx = bi;
        }
        __syncthreads();
    }
}

// generic FPS (small N) for stage 2
template <int PPT>
__global__ void __launch_bounds__(1024) fps_kernel(
    const float* __restrict__ xyz, int N, int npoint,
    int* __restrict__ idx_out, float* __restrict__ newxyz)
{
    const int b = blockIdx.x;
    const int T = blockDim.x;
    const int t = threadIdx.x;
    const float* P = xyz + (size_t)b * N * 3;

    float dist[PPT];
#pragma unroll
    for (int k = 0; k < PPT; k++) dist[k] = 1e10f;

    __shared__ float s_v[32];
    __shared__ int   s_i[32];
    __shared__ float s_far[3];
    __shared__ int   s_faridx;
    if (t == 0) s_faridx = 0;
    __syncthreads();

    for (int it = 0; it < npoint; it++) {
        if (t == 0) {
            int far = s_faridx;
            float fx = P[far * 3 + 0];
            float fy = P[far * 3 + 1];
            float fz = P[far * 3 + 2];
            idx_out[b * npoint + it] = far;
            newxyz[((size_t)b * npoint + it) * 3 + 0] = fx;
            newxyz[((size_t)b * npoint + it) * 3 + 1] = fy;
            newxyz[((size_t)b * npoint + it) * 3 + 2] = fz;
            s_far[0] = fx; s_far[1] = fy; s_far[2] = fz;
        }
        __syncthreads();
        float fx = s_far[0], fy = s_far[1], fz = s_far[2];
        float best = -1.f;
        int bi = 0x7fffffff;
#pragma unroll
        for (int k = 0; k < PPT; k++) {
            int p = t + k * T;
            if (p < N) {
                float dx = __fsub_rn(P[p * 3 + 0], fx);
                float dy = __fsub_rn(P[p * 3 + 1], fy);
                float dz = __fsub_rn(P[p * 3 + 2], fz);
                float d = __fadd_rn(__fadd_rn(__fmul_rn(dx, dx), __fmul_rn(dy, dy)),
                                    __fmul_rn(dz, dz));
                float nd = fminf(dist[k], d);
                dist[k] = nd;
                if (nd > best) { best = nd; bi = p; }
            }
        }
#pragma unroll
        for (int o = 16; o > 0; o >>= 1) {
            float ov = __shfl_down_sync(0xffffffffu, best, o);
            int   oi = __shfl_down_sync(0xffffffffu, bi, o);
            if (ov > best || (ov == best && oi < bi)) { best = ov; bi = oi; }
        }
        if ((t & 31) == 0) { s_v[t >> 5] = best; s_i[t >> 5] = bi; }
        __syncthreads();
        if (t < 32) {
            int nw = T >> 5;
            best = (t < nw) ? s_v[t] : -1.f;
            bi   = (t < nw) ? s_i[t] : 0x7fffffff;
#pragma unroll
            for (int o = 16; o > 0; o >>= 1) {
                float ov = __shfl_down_sync(0xffffffffu, best, o);
                int   oi = __shfl_down_sync(0xffffffffu, bi, o);
                if (ov > best || (ov == best && oi < bi)) { best = ov; bi = oi; }
            }
            if (t == 0) s_faridx = bi;
        }
        __syncthreads();
    }
}

// ---------------------------------------------------------------------------
// Ball query — one warp per center; first nsample (ascending) within radius.
// ---------------------------------------------------------------------------
__global__ void ballquery_kernel(const float* __restrict__ centers,
                                 const float* __restrict__ pts,
                                 int B, int S, int N, float r2, int nsample,
                                 int* __restrict__ out)
{
    int wg = (blockIdx.x * blockDim.x + threadIdx.x) >> 5;
    int lane = threadIdx.x & 31;
    if (wg >= B * S) return;
    int b = wg / S;
    const float* P = pts + (size_t)b * N * 3;
    float cx = centers[(size_t)wg * 3 + 0];
    float cy = centers[(size_t)wg * 3 + 1];
    float cz = centers[(size_t)wg * 3 + 2];
    int* o = out + (size_t)wg * nsample;

    int count = 0;
    int first = -1;
    for (int base = 0; base < N && count < nsample; base += 32) {
        int p = base + lane;
        bool inside = false;
        if (p < N) {
            float dx = __fsub_rn(cx, P[p * 3 + 0]);
            float dy = __fsub_rn(cy, P[p * 3 + 1]);
            float dz = __fsub_rn(cz, P[p * 3 + 2]);
            float d2 = __fadd_rn(__fadd_rn(__fmul_rn(dx, dx), __fmul_rn(dy, dy)),
                                 __fmul_rn(dz, dz));
            inside = d2 < r2;
        }
        unsigned m = __ballot_sync(0xffffffffu, inside);
        if (first < 0 && m) first = base + __ffs(m) - 1;
        if (inside) {
            int pos = count + __popc(m & ((1u << lane) - 1u));
            if (pos < nsample) o[pos] = p;
        }
        count += __popc(m);
    }
    int start = count < nsample ? count : nsample;
    for (int k = start + lane; k < nsample; k += 32) o[k] = first;
}

// ---------------------------------------------------------------------------
// Grouping / concat kernels
// ---------------------------------------------------------------------------
__global__ void group_xyz_kernel(const float* __restrict__ pts,
                                 const float* __restrict__ centers,
                                 const int* __restrict__ idx,
                                 float* __restrict__ out,
                                 int B, int S, int N, int ns, float radius)
{
    unsigned total = (unsigned)B * S * ns * 3;
    unsigned stride = gridDim.x * blockDim.x;
    for (unsigned e = blockIdx.x * blockDim.x + threadIdx.x; e < total; e += stride) {
        int d = e % 3;
        unsigned g = e / 3;
        int pid = idx[g];
        unsigned cidx = g / ns;
        int b = cidx / S;
        float v = __fsub_rn(pts[((size_t)b * N + pid) * 3 + d], centers[(size_t)cidx * 3 + d]);
        out[e] = __fdiv_rn(v, radius);
    }
}

__global__ void group_feat_kernel(const float* __restrict__ pts,
                                  const float* __restrict__ centers,
                                  const int* __restrict__ idx,
                                  const float* __restrict__ feats,
                                  float* __restrict__ out,
                                  int B, int S, int N, int ns, int CF, float radius)
{
    int C = 3 + CF;
    unsigned total = (unsigned)B * S * ns * C;
    unsigned stride = gridDim.x * blockDim.x;
    for (unsigned e = blockIdx.x * blockDim.x + threadIdx.x; e < total; e += stride) {
        int c = e % C;
        unsigned g = e / C;
        int pid = idx[g];
        unsigned cidx = g / ns;
        int b = cidx / S;
        float v;
        if (c < 3) {
            v = __fdiv_rn(__fsub_rn(pts[((size_t)b * N + pid) * 3 + c],
                                    centers[(size_t)cidx * 3 + c]), radius);
        } else {
            v = feats[((size_t)b * N + pid) * CF + (c - 3)];
        }
        out[e] = v;
    }
}

__global__ void concat_sa3_kernel(const float* __restrict__ xyz2,
                                  const float* __restrict__ f2,
                                  float* __restrict__ out, int R, int CF)
{
    int C = 3 + CF;
    unsigned total = (unsigned)R * C;
    unsigned stride = gridDim.x * blockDim.x;
    for (unsigned e = blockIdx.x * blockDim.x + threadIdx.x; e < total; e += stride) {
        int r = e / C;
        int c = e % C;
        out[e] = (c < 3) ? xyz2[(size_t)r * 3 + c] : f2[(size_t)r * CF + (c - 3)];
    }
}

__global__ void concat_comb_kernel(const float* __restrict__ gf,
                                   const float* __restrict__ of,
                                   float* __restrict__ out, int B, int C1, int C2)
{
    int C = C1 + C2;
    unsigned total = (unsigned)B * C;
    unsigned stride = gridDim.x * blockDim.x;
    for (unsigned e = blockIdx.x * blockDim.x + threadIdx.x; e < total; e += stride) {
        int b = e / C;
        int c = e % C;
        out[e] = (c < C1) ? gf[(size_t)b * C1 + c] : of[(size_t)b * C2 + (c - C1)];
    }
}

// ---------------------------------------------------------------------------
// Host-side orchestration
// ---------------------------------------------------------------------------
static inline int cdiv(long a, long b) { return (int)((a + b - 1) / b); }

static int ew_blocks(long total)
{
    int b = cdiv(total, 256);
    return b > 4096 ? 4096 : b;
}

struct BnCtx { float *sum, *sq, *mean, *inv; };

static void launch_gemm(const float* X, const float* W, const float* bias, float* Y,
                        int M, int N, int K,
                        const float* inMean, const float* inInv,
                        float* gsum, float* gsq, int relu_out)
{
    dim3 grid(cdiv(N, 64), cdiv(M, 128));
    gemm_fused_kernel<<<grid, 256>>>(X, W, bias, Y, M, N, K,
                                     inMean, inInv, gsum, gsq, relu_out);
}

// one BN-MLP chain layer: gemm with input-transform + stats, then finalize
static void chain_layer(const float* X, const float* W, float* Y,
                        int M, int N, int K, bool first, const BnCtx& bn)
{
    launch_gemm(X, W, nullptr, Y, M, N, K,
                first ? nullptr : bn.mean, first ? nullptr : bn.inv,
                bn.sum, bn.sq, 0);
    bn_finalize_kernel<<<cdiv(N, 256), 256>>>(bn.sum, bn.sq, bn.mean, bn.inv,
                                              N, 1.f / (float)M);
}

extern "C" void kernel_launch(void* const* d_in, const int* in_sizes, int n_in,
                              void* d_out, int out_size)
{
    (void)in_sizes; (void)n_in; (void)out_size;
    const float* obj   = (const float*)d_in[0];   // [8,20000,3]
    const float* grip  = (const float*)d_in[1];   // [8,512,3]
    const float* sa1w0 = (const float*)d_in[2];
    const float* sa1w1 = (const float*)d_in[3];
    const float* sa1w2 = (const float*)d_in[4];
    const float* sa2w0 = (const float*)d_in[5];
    const float* sa2w1 = (const float*)d_in[6];
    const float* sa2w2 = (const float*)d_in[7];
    const float* sa3w0 = (const float*)d_in[8];
    const float* sa3w1 = (const float*)d_in[9];
    const float* sa3w2 = (const float*)d_in[10];
    const float* gew0  = (const float*)d_in[11];
    const float* gew1  = (const float*)d_in[12];
    const float* gew2  = (const float*)d_in[13];
    const float* hw0   = (const float*)d_in[14];
    const float* hb0   = (const float*)d_in[15];
    const float* hw1   = (const float*)d_in[16];
    const float* hb1   = (const float*)d_in[17];
    const float* hw2   = (const float*)d_in[18];
    const float* hb2   = (const float*)d_in[19];

    float *bufA, *bufB, *f1, *f2, *sa3in, *gfeat, *objf, *comb, *h0, *h1;
    float *xyz1, *xyz2, *bsum, *bsq, *bmean, *binv;
    int *fps1, *fps2, *bq1, *bq2;
    cudaGetSymbolAddress((void**)&bufA,  g_bufA);
    cudaGetSymbolAddress((void**)&bufB,  g_bufB);
    cudaGetSymbolAddress((void**)&f1,    g_f1);
    cudaGetSymbolAddress((void**)&f2,    g_f2);
    cudaGetSymbolAddress((void**)&sa3in, g_sa3in);
    cudaGetSymbolAddress((void**)&gfeat, g_gfeat);
    cudaGetSymbolAddress((void**)&objf,  g_objfeat);
    cudaGetSymbolAddress((void**)&comb,  g_comb);
    cudaGetSymbolAddress((void**)&h0,    g_h0);
    cudaGetSymbolAddress((void**)&h1,    g_h1);
    cudaGetSymbolAddress((void**)&xyz1,  g_xyz1);
    cudaGetSymbolAddress((void**)&xyz2,  g_xyz2);
    cudaGetSymbolAddress((void**)&fps1,  g_fps1);
    cudaGetSymbolAddress((void**)&fps2,  g_fps2);
    cudaGetSymbolAddress((void**)&bq1,   g_bq1);
    cudaGetSymbolAddress((void**)&bq2,   g_bq2);
    cudaGetSymbolAddress((void**)&bsum,  g_bnsum);
    cudaGetSymbolAddress((void**)&bsq,   g_bnsq);
    cudaGetSymbolAddress((void**)&bmean, g_bnmean);
    cudaGetSymbolAddress((void**)&binv,  g_bninv);
    BnCtx bn = {bsum, bsq, bmean, binv};

    const int B = 8, N0 = 20000, G = 512;
    const int S1 = 512, NS1 = 32, S2 = 128, NS2 = 64;
    const float r2_1 = (float)(0.2 * 0.2);
    const float r2_2 = (float)(0.4 * 0.4);

    // zero stats accumulators (finalize re-zeros after each layer)
    bn_zero_kernel<<<1, 256>>>(bsum, bsq, 1024);

    // ---------------- FPS1 first (coords in 160KB smem) ----------------
    cudaFuncSetAttribute(fps1_kernel, cudaFuncAttributeMaxDynamicSharedMemorySize,
                         N0 * (int)sizeof(float2));
    fps1_kernel<<<B, 512, N0 * sizeof(float2)>>>(obj, N0, S1, fps1, xyz1);

    // ---------------- gripper encoder: [8,512,3] -> [8,128] ----------------
    {
        int M = B * G;  // 4096
        chain_layer(grip, gew0, bufB, M, 64, 3, true, bn);
        chain_layer(bufB, gew1, bufA, M, 128, 64, false, bn);
        chain_layer(bufA, gew2, bufB, M, 128, 128, false, bn);
        maxpool_bn_kernel<<<ew_blocks((long)B * 128), 256>>>(bufB, gfeat, B, G, 128,
                                                             bmean, binv);
    }

    // ---------------- SA1: 20000 -> 512 centers, ns=32, r=0.2 ----------------
    {
        int warps = B * S1;
        ballquery_kernel<<<cdiv((long)warps * 32, 128), 128>>>(xyz1, obj, B, S1, N0,
                                                               r2_1, NS1, bq1);
        long gtot = (long)B * S1 * NS1 * 3;
        group_xyz_kernel<<<ew_blocks(gtot), 256>>>(obj, xyz1, bq1, bufA, B, S1, N0,
                                                   NS1, 0.2f);

        int M = B * S1 * NS1;  // 131072
        chain_layer(bufA, sa1w0, bufB, M, 64, 3, true, bn);
        chain_layer(bufB, sa1w1, bufA, M, 64, 64, false, bn);
        chain_layer(bufA, sa1w2, bufB, M, 128, 64, false, bn);
        maxpool_bn_kernel<<<ew_blocks((long)B * S1 * 128), 256>>>(bufB, f1, B * S1,
                                                                  NS1, 128, bmean, binv);
    }

    // ---------------- SA2: 512 -> 128 centers, ns=64, r=0.4 ----------------
    fps_kernel<1><<<B, 512>>>(xyz1, S1, S2, fps2, xyz2);
    {
        int warps = B * S2;
        ballquery_kernel<<<cdiv((long)warps * 32, 128), 128>>>(xyz2, xyz1, B, S2, S1,
                                                               r2_2, NS2, bq2);
        long gtot = (long)B * S2 * NS2 * 131;
        group_feat_kernel<<<ew_blocks(gtot), 256>>>(xyz1, xyz2, bq2, f1, bufA,
                                                    B, S2, S1, NS2, 128, 0.4f);

        int M = B * S2 * NS2;  // 65536
        chain_layer(bufA, sa2w0, bufB, M, 128, 131, true, bn);
        chain_layer(bufB, sa2w1, bufA, M, 128, 128, false, bn);
        chain_layer(bufA, sa2w2, bufB, M, 256, 128, false, bn);
        maxpool_bn_kernel<<<ew_blocks((long)B * S2 * 256), 256>>>(bufB, f2, B * S2,
                                                                  NS2, 256, bmean, binv);
    }

    // ---------------- SA3: group_all on [8,128,259] ----------------
    {
        int M = B * S2;  // 1024
        concat_sa3_kernel<<<ew_blocks((long)M * 259), 256>>>(xyz2, f2, sa3in, M, 256);
        chain_layer(sa3in, sa3w0, bufA, M, 256, 259, true, bn);
        chain_layer(bufA, sa3w1, bufB, M, 512, 256, false, bn);
        chain_layer(bufB, sa3w2, bufA, M, 1024, 512, false, bn);
        maxpool_bn_kernel<<<ew_blocks((long)B * 1024), 256>>>(bufA, objf, B, S2, 1024,
                                                              bmean, binv);
    }

    // ---------------- head ----------------
    {
        concat_comb_kernel<<<ew_blocks((long)B * 1152), 256>>>(gfeat, objf, comb,
                                                               B, 128, 1024);
        bn_col_kernel<<<cdiv(1152, 256), 256>>>(comb, B, 1152, 0);
        launch_gemm(comb, hw0, hb0, h0, B, 512, 1152, nullptr, nullptr,
                    nullptr, nullptr, 0);
        bn_col_kernel<<<cdiv(512, 256), 256>>>(h0, B, 512, 1);
        launch_gemm(h0, hw1, hb1, h1, B, 256, 512, nullptr, nullptr,
                    nullptr, nullptr, 0);
        bn_col_kernel<<<cdiv(256, 256), 256>>>(h1, B, 256, 1);
        launch_gemm(h1, hw2, hb2, (float*)d_out, B, 1, 256, nullptr, nullptr,
                    nullptr, nullptr, 1);
    }
}